// round 1
// baseline (speedup 1.0000x reference)
#include <cuda_runtime.h>
#include <math.h>

// Problem dims (fixed by the reference)
#define HID   2048
#define CH    4096
#define SEQ   4096
#define BATCH 4
#define MROWS (BATCH * SEQ)   // 16384
#define KER   4

// Scratch (allocation-free rule: __device__ globals)
__device__ float g_x[(size_t)MROWS * CH];   // after in-proj
__device__ float g_y[(size_t)MROWS * CH];   // after conv+silu

// ---------------------------------------------------------------------------
// SGEMM: C[m,n] = sum_k A[m,k] * B[n,k] + bias[n]
// A: [M,K] row-major, B: [N,K] row-major (both K-contiguous -> "NT" gemm)
// 128x128 tile, KT=8, 256 threads, 8x8 per thread.
// ---------------------------------------------------------------------------
#define TILE 128
#define KT   8

__global__ __launch_bounds__(256, 2)
void sgemm_nt_bias(const float* __restrict__ A,
                   const float* __restrict__ B,
                   const float* __restrict__ bias,
                   float* __restrict__ C,
                   int M, int N, int K)
{
    __shared__ float As[KT][TILE];
    __shared__ float Bs[KT][TILE];

    const int tid = threadIdx.x;          // 0..255
    const int bm  = blockIdx.y * TILE;
    const int bn  = blockIdx.x * TILE;

    // global-load mapping: each thread loads one float4 of A and one of B per k-step
    const int lr = tid >> 1;              // 0..127 (row within tile)
    const int lk = (tid & 1) << 2;        // 0 or 4 (k offset)

    // compute mapping
    const int tx = tid & 15;              // 0..15 -> 8 cols each
    const int ty = tid >> 4;              // 0..15 -> 8 rows each

    const float* Ap = A + (size_t)(bm + lr) * K + lk;
    const float* Bp = B + (size_t)(bn + lr) * K + lk;

    float acc[8][8];
#pragma unroll
    for (int i = 0; i < 8; i++)
#pragma unroll
        for (int j = 0; j < 8; j++) acc[i][j] = 0.0f;

    for (int k0 = 0; k0 < K; k0 += KT) {
        const float4 a4 = *reinterpret_cast<const float4*>(Ap + k0);
        const float4 b4 = *reinterpret_cast<const float4*>(Bp + k0);

        __syncthreads();  // previous iteration's smem reads done
        As[lk + 0][lr] = a4.x;  As[lk + 1][lr] = a4.y;
        As[lk + 2][lr] = a4.z;  As[lk + 3][lr] = a4.w;
        Bs[lk + 0][lr] = b4.x;  Bs[lk + 1][lr] = b4.y;
        Bs[lk + 2][lr] = b4.z;  Bs[lk + 3][lr] = b4.w;
        __syncthreads();

#pragma unroll
        for (int kk = 0; kk < KT; kk++) {
            const float4 a0 = *reinterpret_cast<const float4*>(&As[kk][ty * 8]);
            const float4 a1 = *reinterpret_cast<const float4*>(&As[kk][ty * 8 + 4]);
            const float4 b0 = *reinterpret_cast<const float4*>(&Bs[kk][tx * 8]);
            const float4 b1 = *reinterpret_cast<const float4*>(&Bs[kk][tx * 8 + 4]);
            const float ar[8] = {a0.x, a0.y, a0.z, a0.w, a1.x, a1.y, a1.z, a1.w};
            const float br[8] = {b0.x, b0.y, b0.z, b0.w, b1.x, b1.y, b1.z, b1.w};
#pragma unroll
            for (int i = 0; i < 8; i++)
#pragma unroll
                for (int j = 0; j < 8; j++)
                    acc[i][j] = fmaf(ar[i], br[j], acc[i][j]);
        }
    }

    // epilogue: fused bias, float4 stores
    const int colBase = bn + tx * 8;
    const float4 bia0 = *reinterpret_cast<const float4*>(bias + colBase);
    const float4 bia1 = *reinterpret_cast<const float4*>(bias + colBase + 4);
#pragma unroll
    for (int i = 0; i < 8; i++) {
        const int row = bm + ty * 8 + i;
        float* Crow = C + (size_t)row * N + colBase;
        float4 o0, o1;
        o0.x = acc[i][0] + bia0.x;  o0.y = acc[i][1] + bia0.y;
        o0.z = acc[i][2] + bia0.z;  o0.w = acc[i][3] + bia0.w;
        o1.x = acc[i][4] + bia1.x;  o1.y = acc[i][5] + bia1.y;
        o1.z = acc[i][6] + bia1.z;  o1.w = acc[i][7] + bia1.w;
        *reinterpret_cast<float4*>(Crow)     = o0;
        *reinterpret_cast<float4*>(Crow + 4) = o1;
    }
}

// ---------------------------------------------------------------------------
// Causal depthwise conv (K=4) + bias + SiLU, elementwise over [MROWS, CH].
// y[m,c] = silu( cb[c] + sum_{k=0..3, s-3+k>=0} x[m-3+k, c] * cw[c*4+k] )
// where s = m % SEQ (per-batch causal boundary).
// ---------------------------------------------------------------------------
__global__ __launch_bounds__(256)
void conv_silu(const float* __restrict__ x,
               const float* __restrict__ cw,
               const float* __restrict__ cb,
               float* __restrict__ y)
{
    const size_t idx = (size_t)blockIdx.x * blockDim.x + threadIdx.x;
    if (idx >= (size_t)MROWS * CH) return;
    const int c = (int)(idx & (CH - 1));
    const int m = (int)(idx >> 12);        // CH = 4096 = 2^12
    const int s = m & (SEQ - 1);           // SEQ = 4096

    float acc = cb[c];
    const float4 w4 = *reinterpret_cast<const float4*>(cw + (size_t)c * KER);
    const float w[4] = {w4.x, w4.y, w4.z, w4.w};
#pragma unroll
    for (int k = 0; k < KER; k++) {
        const int ds = k - (KER - 1);      // -3..0
        if (s + ds >= 0)
            acc = fmaf(x[idx + (long long)ds * CH], w[k], acc);
    }
    // SiLU
    const float sig = 1.0f / (1.0f + __expf(-acc));
    y[idx] = acc * sig;
}

// ---------------------------------------------------------------------------
// Launch
// Inputs (metadata order): hidden_states, w_in, b_in, conv_w, conv_b, w_out, b_out
// ---------------------------------------------------------------------------
extern "C" void kernel_launch(void* const* d_in, const int* in_sizes, int n_in,
                              void* d_out, int out_size)
{
    const float* hs     = (const float*)d_in[0];  // [4,4096,2048]
    const float* w_in   = (const float*)d_in[1];  // [4096,2048]
    const float* b_in   = (const float*)d_in[2];  // [4096]
    const float* conv_w = (const float*)d_in[3];  // [4096,1,4]
    const float* conv_b = (const float*)d_in[4];  // [4096]
    const float* w_out  = (const float*)d_in[5];  // [2048,4096]
    const float* b_out  = (const float*)d_in[6];  // [2048]
    float* out = (float*)d_out;                   // [4,4096,2048]

    float* xbuf;
    float* ybuf;
    cudaGetSymbolAddress((void**)&xbuf, g_x);
    cudaGetSymbolAddress((void**)&ybuf, g_y);

    // GEMM1: x = hs @ w_in^T + b_in   -> [16384, 4096]
    {
        dim3 grid(CH / TILE, MROWS / TILE);   // (32, 128)
        sgemm_nt_bias<<<grid, 256>>>(hs, w_in, b_in, xbuf, MROWS, CH, HID);
    }

    // conv + SiLU -> ybuf
    {
        const size_t total = (size_t)MROWS * CH;
        const int threads = 256;
        const int blocks = (int)((total + threads - 1) / threads);
        conv_silu<<<blocks, threads>>>(xbuf, conv_w, conv_b, ybuf);
    }

    // GEMM2: out = y @ w_out^T + b_out -> [16384, 2048]
    {
        dim3 grid(HID / TILE, MROWS / TILE);  // (16, 128)
        sgemm_nt_bias<<<grid, 256>>>(ybuf, w_out, b_out, out, MROWS, HID, CH);
    }
}

// round 3
// speedup vs baseline: 2.8650x; 2.8650x over previous
#include <cuda_runtime.h>
#include <cuda_bf16.h>
#include <cstdint>

// ---------------------------------------------------------------------------
// Problem dims
// ---------------------------------------------------------------------------
#define HID   2048
#define CH    4096
#define SEQ   4096
#define BATCH 4
#define MROWS (BATCH * SEQ)   // 16384

// ---------------------------------------------------------------------------
// Device scratch (allocation-free rule)
// ---------------------------------------------------------------------------
__device__ __nv_bfloat16 g_hs_h [(size_t)MROWS * HID];
__device__ __nv_bfloat16 g_hs_l [(size_t)MROWS * HID];
__device__ __nv_bfloat16 g_win_h[(size_t)CH * HID];
__device__ __nv_bfloat16 g_win_l[(size_t)CH * HID];
__device__ __nv_bfloat16 g_wout_h[(size_t)HID * CH];
__device__ __nv_bfloat16 g_wout_l[(size_t)HID * CH];
__device__ float         g_x  [(size_t)MROWS * CH];   // after in-proj (fp32)
__device__ __nv_bfloat16 g_yh [(size_t)MROWS * CH];   // conv+silu, bf16 hi
__device__ __nv_bfloat16 g_yl [(size_t)MROWS * CH];   // conv+silu, bf16 lo

// ---------------------------------------------------------------------------
// PTX helpers (arch-generic only: cp.async / ldmatrix / mma.sync)
// ---------------------------------------------------------------------------
__device__ __forceinline__ uint32_t smem_u32(const void* p) {
    uint32_t a;
    asm("{ .reg .u64 t; cvta.to.shared.u64 t, %1; cvt.u32.u64 %0, t; }" : "=r"(a) : "l"(p));
    return a;
}
__device__ __forceinline__ void cp16(uint32_t dst, const void* src) {
    asm volatile("cp.async.cg.shared.global [%0], [%1], 16;" :: "r"(dst), "l"(src));
}
__device__ __forceinline__ void cp_commit() { asm volatile("cp.async.commit_group;" ::: "memory"); }
__device__ __forceinline__ void cp_wait1()  { asm volatile("cp.async.wait_group 1;"  ::: "memory"); }
__device__ __forceinline__ void cp_wait0()  { asm volatile("cp.async.wait_group 0;"  ::: "memory"); }

__device__ __forceinline__ void ldsm_x4(uint32_t* r, uint32_t addr) {
    asm volatile("ldmatrix.sync.aligned.m8n8.x4.shared.b16 {%0,%1,%2,%3}, [%4];"
        : "=r"(r[0]), "=r"(r[1]), "=r"(r[2]), "=r"(r[3]) : "r"(addr));
}
__device__ __forceinline__ void mma16816(float* c, const uint32_t* a, const uint32_t* b) {
    asm volatile(
        "mma.sync.aligned.m16n8k16.row.col.f32.bf16.bf16.f32 "
        "{%0,%1,%2,%3}, {%4,%5,%6,%7}, {%8,%9}, {%0,%1,%2,%3};"
        : "+f"(c[0]), "+f"(c[1]), "+f"(c[2]), "+f"(c[3])
        : "r"(a[0]), "r"(a[1]), "r"(a[2]), "r"(a[3]), "r"(b[0]), "r"(b[1]));
}

// ---------------------------------------------------------------------------
// GEMM: C[m,n] = sum_k A[m,k]*B[n,k] + bias[n], bf16x3 split on mma.sync.
// CTA tile 128x128, 8 warps (warp tile 32x64), BK=32, 3-stage cp.async.
// smem per matrix tile: 128 rows x 40 bf16 (pad 8) = 10240 B.
// ---------------------------------------------------------------------------
#define BK    32
#define LDA   40          // padded row stride in bf16 elements
#define MATB  (128 * LDA) // elements per matrix tile (5120)
#define STAGE_ELEMS (4 * MATB)           // Ah, Al, Bh, Bl
#define STAGES 3
#define GEMM_SMEM (STAGES * STAGE_ELEMS * 2)  // 122880 bytes

__global__ void __launch_bounds__(256, 1)
gemm_mma_bf16x3(const __nv_bfloat16* __restrict__ Ah, const __nv_bfloat16* __restrict__ Al,
                const __nv_bfloat16* __restrict__ Bh, const __nv_bfloat16* __restrict__ Bl,
                const float* __restrict__ bias, float* __restrict__ C,
                int M, int N, int K)
{
    extern __shared__ __align__(16) char smraw[];
    __nv_bfloat16* sm = reinterpret_cast<__nv_bfloat16*>(smraw);
    const uint32_t sbase = smem_u32(sm);

    const int tid  = threadIdx.x;
    const int wid  = tid >> 5;
    const int lane = tid & 31;
    const int bm   = blockIdx.y * 128;
    const int bn   = blockIdx.x * 128;
    const int wm   = (wid & 3) * 32;     // warp row offset
    const int wn   = (wid >> 2) * 64;    // warp col offset

    float acc[2][8][4];
#pragma unroll
    for (int i = 0; i < 2; i++)
#pragma unroll
        for (int j = 0; j < 8; j++)
#pragma unroll
            for (int k = 0; k < 4; k++) acc[i][j][k] = 0.0f;

    const int nchunks = K / BK;

    // --- async stage loader: 2 cp16 per thread per matrix ---
    auto load_stage = [&](int slot, int k0) {
        const uint32_t st = sbase + (uint32_t)slot * STAGE_ELEMS * 2;
#pragma unroll
        for (int i = 0; i < 2; i++) {
            const int c   = tid + 256 * i;       // 0..511
            const int row = c >> 2;
            const int kc  = (c & 3) * 8;
            const uint32_t soff = (uint32_t)(row * LDA + kc) * 2;
            const size_t gA = (size_t)(bm + row) * K + k0 + kc;
            const size_t gB = (size_t)(bn + row) * K + k0 + kc;
            cp16(st + soff,              Ah + gA);
            cp16(st + MATB * 2 + soff,   Al + gA);
            cp16(st + MATB * 4 + soff,   Bh + gB);
            cp16(st + MATB * 6 + soff,   Bl + gB);
        }
        cp_commit();
    };

    // prologue: chunks 0,1
    load_stage(0, 0);
    load_stage(1, BK);

    for (int i = 0; i < nchunks; i++) {
        if (i < nchunks - 2) cp_wait1(); else cp_wait0();
        __syncthreads();

        // prefetch chunk i+2 into slot (i+2)%3 (holds chunk i-1, already consumed)
        if (i + 2 < nchunks) load_stage((i + 2) % STAGES, (i + 2) * BK);

        const uint32_t st  = sbase + (uint32_t)(i % STAGES) * STAGE_ELEMS * 2;
        const uint32_t sAh = st;
        const uint32_t sAl = st + MATB * 2;
        const uint32_t sBh = st + MATB * 4;
        const uint32_t sBl = st + MATB * 6;

#pragma unroll
        for (int kk = 0; kk < 2; kk++) {           // two k16 sub-steps
            uint32_t ah[2][4], al[2][4];
#pragma unroll
            for (int mt = 0; mt < 2; mt++) {
                const int row = wm + mt * 16 + (lane & 15);
                const int col = kk * 16 + (lane >> 4) * 8;
                const uint32_t off = (uint32_t)(row * LDA + col) * 2;
                ldsm_x4(ah[mt], sAh + off);
                ldsm_x4(al[mt], sAl + off);
            }
            uint32_t bh[4][4], bl[4][4];
#pragma unroll
            for (int q = 0; q < 4; q++) {          // n-tile pairs
                const int nrow = wn + q * 16 + (lane & 7) + ((lane >> 4) << 3);
                const int col  = kk * 16 + ((lane >> 3) & 1) * 8;
                const uint32_t off = (uint32_t)(nrow * LDA + col) * 2;
                ldsm_x4(bh[q], sBh + off);
                ldsm_x4(bl[q], sBl + off);
            }
#pragma unroll
            for (int mt = 0; mt < 2; mt++)
#pragma unroll
                for (int q = 0; q < 4; q++)
#pragma unroll
                    for (int h = 0; h < 2; h++) {
                        float* c = acc[mt][q * 2 + h];
                        mma16816(c, ah[mt], &bh[q][h * 2]);
                        mma16816(c, al[mt], &bh[q][h * 2]);
                        mma16816(c, ah[mt], &bl[q][h * 2]);
                    }
        }
        __syncthreads();
    }

    // --- epilogue: fused bias ---
    const int r  = lane >> 2;
    const int cc = (lane & 3) * 2;
#pragma unroll
    for (int mt = 0; mt < 2; mt++) {
        const int row0 = bm + wm + mt * 16;
#pragma unroll
        for (int nt = 0; nt < 8; nt++) {
            const int col0 = bn + wn + nt * 8;
            const float2 bv = *reinterpret_cast<const float2*>(bias + col0 + cc);
            float* p0 = C + (size_t)(row0 + r) * N + col0 + cc;
            float* p1 = C + (size_t)(row0 + r + 8) * N + col0 + cc;
            float2 o0, o1;
            o0.x = acc[mt][nt][0] + bv.x;  o0.y = acc[mt][nt][1] + bv.y;
            o1.x = acc[mt][nt][2] + bv.x;  o1.y = acc[mt][nt][3] + bv.y;
            *reinterpret_cast<float2*>(p0) = o0;
            *reinterpret_cast<float2*>(p1) = o1;
        }
    }
}

// ---------------------------------------------------------------------------
// fp32 -> bf16 (hi, lo) split; n4 = n/4 float4 elements
// ---------------------------------------------------------------------------
__global__ void __launch_bounds__(256)
split_fp32(const float* __restrict__ src, __nv_bfloat16* __restrict__ hi,
           __nv_bfloat16* __restrict__ lo, long long n4)
{
    const long long i = (long long)blockIdx.x * blockDim.x + threadIdx.x;
    if (i >= n4) return;
    const float4 v = reinterpret_cast<const float4*>(src)[i];
    __nv_bfloat16 h0 = __float2bfloat16(v.x), h1 = __float2bfloat16(v.y);
    __nv_bfloat16 h2 = __float2bfloat16(v.z), h3 = __float2bfloat16(v.w);
    __nv_bfloat16 l0 = __float2bfloat16(v.x - __bfloat162float(h0));
    __nv_bfloat16 l1 = __float2bfloat16(v.y - __bfloat162float(h1));
    __nv_bfloat16 l2 = __float2bfloat16(v.z - __bfloat162float(h2));
    __nv_bfloat16 l3 = __float2bfloat16(v.w - __bfloat162float(h3));
    __nv_bfloat162 p;
    p.x = h0; p.y = h1; reinterpret_cast<__nv_bfloat162*>(hi)[2 * i]     = p;
    p.x = h2; p.y = h3; reinterpret_cast<__nv_bfloat162*>(hi)[2 * i + 1] = p;
    p.x = l0; p.y = l1; reinterpret_cast<__nv_bfloat162*>(lo)[2 * i]     = p;
    p.x = l2; p.y = l3; reinterpret_cast<__nv_bfloat162*>(lo)[2 * i + 1] = p;
}

// ---------------------------------------------------------------------------
// Causal depthwise conv (K=4) + bias + SiLU, rolling window along seq,
// emitting bf16 hi/lo directly.
// ---------------------------------------------------------------------------
#define SCH 256
__global__ void __launch_bounds__(256)
conv_silu_split(const float* __restrict__ x, const float* __restrict__ cw,
                const float* __restrict__ cb,
                __nv_bfloat16* __restrict__ yh, __nv_bfloat16* __restrict__ yl)
{
    const int c  = blockIdx.x * 256 + threadIdx.x;   // channel
    const int b  = blockIdx.z;
    const int s0 = blockIdx.y * SCH;

    const float4 w4 = *reinterpret_cast<const float4*>(cw + (size_t)c * 4);
    const float bias = cb[c];
    const size_t base = ((size_t)b * SEQ) * CH + c;

    float xm3, xm2, xm1;
    if (s0 == 0) { xm3 = xm2 = xm1 = 0.0f; }
    else {
        xm3 = x[base + (size_t)(s0 - 3) * CH];
        xm2 = x[base + (size_t)(s0 - 2) * CH];
        xm1 = x[base + (size_t)(s0 - 1) * CH];
    }

    for (int s = s0; s < s0 + SCH; s++) {
        const float xc = x[base + (size_t)s * CH];
        float acc = bias;
        acc = fmaf(w4.x, xm3, acc);
        acc = fmaf(w4.y, xm2, acc);
        acc = fmaf(w4.z, xm1, acc);
        acc = fmaf(w4.w, xc,  acc);
        const float v = acc / (1.0f + __expf(-acc));
        const __nv_bfloat16 h = __float2bfloat16(v);
        const __nv_bfloat16 l = __float2bfloat16(v - __bfloat162float(h));
        yh[base + (size_t)s * CH] = h;
        yl[base + (size_t)s * CH] = l;
        xm3 = xm2; xm2 = xm1; xm1 = xc;
    }
}

// ---------------------------------------------------------------------------
// Launch: hidden_states, w_in, b_in, conv_w, conv_b, w_out, b_out
// ---------------------------------------------------------------------------
extern "C" void kernel_launch(void* const* d_in, const int* in_sizes, int n_in,
                              void* d_out, int out_size)
{
    const float* hs     = (const float*)d_in[0];
    const float* w_in   = (const float*)d_in[1];
    const float* b_in   = (const float*)d_in[2];
    const float* conv_w = (const float*)d_in[3];
    const float* conv_b = (const float*)d_in[4];
    const float* w_out  = (const float*)d_in[5];
    const float* b_out  = (const float*)d_in[6];
    float* out = (float*)d_out;

    __nv_bfloat16 *hs_h, *hs_l, *win_h, *win_l, *wout_h, *wout_l, *yh, *yl;
    float *xbuf;
    cudaGetSymbolAddress((void**)&hs_h,  g_hs_h);
    cudaGetSymbolAddress((void**)&hs_l,  g_hs_l);
    cudaGetSymbolAddress((void**)&win_h, g_win_h);
    cudaGetSymbolAddress((void**)&win_l, g_win_l);
    cudaGetSymbolAddress((void**)&wout_h, g_wout_h);
    cudaGetSymbolAddress((void**)&wout_l, g_wout_l);
    cudaGetSymbolAddress((void**)&xbuf, g_x);
    cudaGetSymbolAddress((void**)&yh,   g_yh);
    cudaGetSymbolAddress((void**)&yl,   g_yl);

    cudaFuncSetAttribute(gemm_mma_bf16x3, cudaFuncAttributeMaxDynamicSharedMemorySize, GEMM_SMEM);

    // Split inputs to bf16 hi/lo
    {
        long long n4 = (long long)MROWS * HID / 4;
        split_fp32<<<(unsigned)(n4 / 256), 256>>>(hs, hs_h, hs_l, n4);
        n4 = (long long)CH * HID / 4;
        split_fp32<<<(unsigned)(n4 / 256), 256>>>(w_in, win_h, win_l, n4);
        n4 = (long long)HID * CH / 4;
        split_fp32<<<(unsigned)(n4 / 256), 256>>>(w_out, wout_h, wout_l, n4);
    }

    // GEMM1: x = hs @ w_in^T + b_in   [16384, 4096]
    {
        dim3 grid(CH / 128, MROWS / 128);   // (32, 128)
        gemm_mma_bf16x3<<<grid, 256, GEMM_SMEM>>>(hs_h, hs_l, win_h, win_l, b_in, xbuf,
                                                  MROWS, CH, HID);
    }

    // conv + SiLU -> y (bf16 hi/lo)
    {
        dim3 grid(CH / 256, SEQ / SCH, BATCH);  // (16, 16, 4)
        conv_silu_split<<<grid, 256>>>(xbuf, conv_w, conv_b, yh, yl);
    }

    // GEMM2: out = y @ w_out^T + b_out  [16384, 2048]
    {
        dim3 grid(HID / 128, MROWS / 128);  // (16, 128)
        gemm_mma_bf16x3<<<grid, 256, GEMM_SMEM>>>(yh, yl, wout_h, wout_l, b_out, out,
                                                  MROWS, HID, CH);
    }
}

// round 4
// speedup vs baseline: 4.4627x; 1.5577x over previous
#include <cuda_runtime.h>
#include <cuda_fp16.h>
#include <cstdint>

// ---------------------------------------------------------------------------
// Problem dims
// ---------------------------------------------------------------------------
#define HID   2048
#define CH    4096
#define SEQ   4096
#define BATCH 4
#define MROWS (BATCH * SEQ)   // 16384

// ---------------------------------------------------------------------------
// Device scratch (allocation-free rule)
// ---------------------------------------------------------------------------
__device__ __half g_hs16  [(size_t)MROWS * HID];   // hs as fp16
__device__ __half g_win_h [(size_t)CH * HID];
__device__ __half g_win_l [(size_t)CH * HID];
__device__ __half g_wout_h[(size_t)HID * CH];
__device__ __half g_wout_l[(size_t)HID * CH];
__device__ float  g_x     [(size_t)MROWS * CH];    // after in-proj (fp32)
__device__ __half g_y     [(size_t)MROWS * CH];    // conv+silu (fp16)

// ---------------------------------------------------------------------------
// PTX helpers (arch-generic: cp.async / ldmatrix / mma.sync)
// ---------------------------------------------------------------------------
__device__ __forceinline__ uint32_t smem_u32(const void* p) {
    uint32_t a;
    asm("{ .reg .u64 t; cvta.to.shared.u64 t, %1; cvt.u32.u64 %0, t; }" : "=r"(a) : "l"(p));
    return a;
}
__device__ __forceinline__ void cp16(uint32_t dst, const void* src) {
    asm volatile("cp.async.cg.shared.global [%0], [%1], 16;" :: "r"(dst), "l"(src));
}
__device__ __forceinline__ void cp_commit() { asm volatile("cp.async.commit_group;" ::: "memory"); }
__device__ __forceinline__ void cp_wait1()  { asm volatile("cp.async.wait_group 1;"  ::: "memory"); }
__device__ __forceinline__ void cp_wait0()  { asm volatile("cp.async.wait_group 0;"  ::: "memory"); }

__device__ __forceinline__ void ldsm_x4(uint32_t* r, uint32_t addr) {
    asm volatile("ldmatrix.sync.aligned.m8n8.x4.shared.b16 {%0,%1,%2,%3}, [%4];"
        : "=r"(r[0]), "=r"(r[1]), "=r"(r[2]), "=r"(r[3]) : "r"(addr));
}
__device__ __forceinline__ void mma16816(float* c, const uint32_t* a, const uint32_t* b) {
    asm volatile(
        "mma.sync.aligned.m16n8k16.row.col.f32.f16.f16.f32 "
        "{%0,%1,%2,%3}, {%4,%5,%6,%7}, {%8,%9}, {%0,%1,%2,%3};"
        : "+f"(c[0]), "+f"(c[1]), "+f"(c[2]), "+f"(c[3])
        : "r"(a[0]), "r"(a[1]), "r"(a[2]), "r"(a[3]), "r"(b[0]), "r"(b[1]));
}

// ---------------------------------------------------------------------------
// GEMM: C[m,n] = sum_k A[m,k]*(Bh[n,k]+Bl[n,k]) + bias[n]
// A single fp16 [M,K]; B split fp16 hi/lo [N,K].  2 MMA passes per fragment.
// CTA tile 128x128, 8 warps (warp tile 32x64), BK=32, 3-stage cp.async.
// smem/stage: 3 tiles x 128 x 40(fp16) = 30720 B; 3 stages = 92160 B -> occ 2.
// ---------------------------------------------------------------------------
#define BK    32
#define LDA   40
#define MATB  (128 * LDA)                 // 5120 elems / tile
#define STAGE_ELEMS (3 * MATB)            // A, Bh, Bl
#define STAGES 3
#define GEMM_SMEM (STAGES * STAGE_ELEMS * 2)  // 92160 bytes

__global__ void __launch_bounds__(256, 2)
gemm_fp16x2(const __half* __restrict__ A,
            const __half* __restrict__ Bh, const __half* __restrict__ Bl,
            const float* __restrict__ bias, float* __restrict__ C,
            int M, int N, int K)
{
    extern __shared__ __align__(16) char smraw[];
    const uint32_t sbase = smem_u32(smraw);

    const int tid  = threadIdx.x;
    const int wid  = tid >> 5;
    const int lane = tid & 31;
    const int bm   = blockIdx.y * 128;
    const int bn   = blockIdx.x * 128;
    const int wm   = (wid & 3) * 32;     // warp row offset
    const int wn   = (wid >> 2) * 64;    // warp col offset

    float acc[2][8][4];
#pragma unroll
    for (int i = 0; i < 2; i++)
#pragma unroll
        for (int j = 0; j < 8; j++)
#pragma unroll
            for (int k = 0; k < 4; k++) acc[i][j][k] = 0.0f;

    const int nchunks = K / BK;

    // stage loader: 2 cp16 per thread per matrix (A, Bh, Bl)
    auto load_stage = [&](int slot, int k0) {
        const uint32_t st = sbase + (uint32_t)slot * STAGE_ELEMS * 2;
#pragma unroll
        for (int i = 0; i < 2; i++) {
            const int c   = tid + 256 * i;       // 0..511
            const int row = c >> 2;
            const int kc  = (c & 3) * 8;
            const uint32_t soff = (uint32_t)(row * LDA + kc) * 2;
            const size_t gA = (size_t)(bm + row) * K + k0 + kc;
            const size_t gB = (size_t)(bn + row) * K + k0 + kc;
            cp16(st + soff,             A  + gA);
            cp16(st + MATB * 2 + soff,  Bh + gB);
            cp16(st + MATB * 4 + soff,  Bl + gB);
        }
        cp_commit();
    };

    load_stage(0, 0);
    load_stage(1, BK);

    for (int i = 0; i < nchunks; i++) {
        if (i < nchunks - 2) cp_wait1(); else cp_wait0();
        __syncthreads();

        if (i + 2 < nchunks) load_stage((i + 2) % STAGES, (i + 2) * BK);

        const uint32_t st  = sbase + (uint32_t)(i % STAGES) * STAGE_ELEMS * 2;
        const uint32_t sA  = st;
        const uint32_t sBh = st + MATB * 2;
        const uint32_t sBl = st + MATB * 4;

#pragma unroll
        for (int kk = 0; kk < 2; kk++) {           // two k16 sub-steps
            uint32_t a[2][4];
#pragma unroll
            for (int mt = 0; mt < 2; mt++) {
                const int row = wm + mt * 16 + (lane & 15);
                const int col = kk * 16 + (lane >> 4) * 8;
                ldsm_x4(a[mt], sA + (uint32_t)(row * LDA + col) * 2);
            }
            uint32_t bh[4][4], bl[4][4];
#pragma unroll
            for (int q = 0; q < 4; q++) {
                const int nrow = wn + q * 16 + (lane & 7) + ((lane >> 4) << 3);
                const int col  = kk * 16 + ((lane >> 3) & 1) * 8;
                const uint32_t off = (uint32_t)(nrow * LDA + col) * 2;
                ldsm_x4(bh[q], sBh + off);
                ldsm_x4(bl[q], sBl + off);
            }
#pragma unroll
            for (int mt = 0; mt < 2; mt++)
#pragma unroll
                for (int q = 0; q < 4; q++)
#pragma unroll
                    for (int h = 0; h < 2; h++) {
                        float* c = acc[mt][q * 2 + h];
                        mma16816(c, a[mt], &bh[q][h * 2]);
                        mma16816(c, a[mt], &bl[q][h * 2]);
                    }
        }
        // single barrier per iteration (top of loop) is sufficient:
        // slot (i+2)%3 was last read in iter i-1, ordered by iter i's sync.
    }

    // --- epilogue: fused bias ---
    const int r  = lane >> 2;
    const int cc = (lane & 3) * 2;
#pragma unroll
    for (int mt = 0; mt < 2; mt++) {
        const int row0 = bm + wm + mt * 16;
#pragma unroll
        for (int nt = 0; nt < 8; nt++) {
            const int col0 = bn + wn + nt * 8;
            const float2 bv = *reinterpret_cast<const float2*>(bias + col0 + cc);
            float* p0 = C + (size_t)(row0 + r) * N + col0 + cc;
            float* p1 = C + (size_t)(row0 + r + 8) * N + col0 + cc;
            float2 o0, o1;
            o0.x = acc[mt][nt][0] + bv.x;  o0.y = acc[mt][nt][1] + bv.y;
            o1.x = acc[mt][nt][2] + bv.x;  o1.y = acc[mt][nt][3] + bv.y;
            *reinterpret_cast<float2*>(p0) = o0;
            *reinterpret_cast<float2*>(p1) = o1;
        }
    }
}

// ---------------------------------------------------------------------------
// fp32 -> fp16 plain convert (activations)
// ---------------------------------------------------------------------------
__global__ void __launch_bounds__(256)
convert_fp16(const float* __restrict__ src, __half* __restrict__ dst, long long n4)
{
    const long long i = (long long)blockIdx.x * blockDim.x + threadIdx.x;
    if (i >= n4) return;
    const float4 v = reinterpret_cast<const float4*>(src)[i];
    __half2 p0, p1;
    p0.x = __float2half(v.x); p0.y = __float2half(v.y);
    p1.x = __float2half(v.z); p1.y = __float2half(v.w);
    reinterpret_cast<__half2*>(dst)[2 * i]     = p0;
    reinterpret_cast<__half2*>(dst)[2 * i + 1] = p1;
}

// ---------------------------------------------------------------------------
// fp32 -> fp16 (hi, lo) split (weights)
// ---------------------------------------------------------------------------
__global__ void __launch_bounds__(256)
split_fp16(const float* __restrict__ src, __half* __restrict__ hi,
           __half* __restrict__ lo, long long n4)
{
    const long long i = (long long)blockIdx.x * blockDim.x + threadIdx.x;
    if (i >= n4) return;
    const float4 v = reinterpret_cast<const float4*>(src)[i];
    const __half h0 = __float2half(v.x), h1 = __float2half(v.y);
    const __half h2 = __float2half(v.z), h3 = __float2half(v.w);
    __half2 ph0, ph1, pl0, pl1;
    ph0.x = h0; ph0.y = h1; ph1.x = h2; ph1.y = h3;
    pl0.x = __float2half(v.x - __half2float(h0));
    pl0.y = __float2half(v.y - __half2float(h1));
    pl1.x = __float2half(v.z - __half2float(h2));
    pl1.y = __float2half(v.w - __half2float(h3));
    reinterpret_cast<__half2*>(hi)[2 * i]     = ph0;
    reinterpret_cast<__half2*>(hi)[2 * i + 1] = ph1;
    reinterpret_cast<__half2*>(lo)[2 * i]     = pl0;
    reinterpret_cast<__half2*>(lo)[2 * i + 1] = pl1;
}

// ---------------------------------------------------------------------------
// Causal depthwise conv (K=4) + bias + SiLU -> fp16
// ---------------------------------------------------------------------------
#define SCH 256
__global__ void __launch_bounds__(256)
conv_silu(const float* __restrict__ x, const float* __restrict__ cw,
          const float* __restrict__ cb, __half* __restrict__ y)
{
    const int c  = blockIdx.x * 256 + threadIdx.x;   // channel
    const int b  = blockIdx.z;
    const int s0 = blockIdx.y * SCH;

    const float4 w4 = *reinterpret_cast<const float4*>(cw + (size_t)c * 4);
    const float bias = cb[c];
    const size_t base = ((size_t)b * SEQ) * CH + c;

    float xm3, xm2, xm1;
    if (s0 == 0) { xm3 = xm2 = xm1 = 0.0f; }
    else {
        xm3 = x[base + (size_t)(s0 - 3) * CH];
        xm2 = x[base + (size_t)(s0 - 2) * CH];
        xm1 = x[base + (size_t)(s0 - 1) * CH];
    }

    for (int s = s0; s < s0 + SCH; s++) {
        const float xc = x[base + (size_t)s * CH];
        float acc = bias;
        acc = fmaf(w4.x, xm3, acc);
        acc = fmaf(w4.y, xm2, acc);
        acc = fmaf(w4.z, xm1, acc);
        acc = fmaf(w4.w, xc,  acc);
        const float v = acc / (1.0f + __expf(-acc));
        y[base + (size_t)s * CH] = __float2half(v);
        xm3 = xm2; xm2 = xm1; xm1 = xc;
    }
}

// ---------------------------------------------------------------------------
// Launch: hidden_states, w_in, b_in, conv_w, conv_b, w_out, b_out
// ---------------------------------------------------------------------------
extern "C" void kernel_launch(void* const* d_in, const int* in_sizes, int n_in,
                              void* d_out, int out_size)
{
    const float* hs     = (const float*)d_in[0];
    const float* w_in   = (const float*)d_in[1];
    const float* b_in   = (const float*)d_in[2];
    const float* conv_w = (const float*)d_in[3];
    const float* conv_b = (const float*)d_in[4];
    const float* w_out  = (const float*)d_in[5];
    const float* b_out  = (const float*)d_in[6];
    float* out = (float*)d_out;

    __half *hs16, *win_h, *win_l, *wout_h, *wout_l, *ybuf;
    float *xbuf;
    cudaGetSymbolAddress((void**)&hs16,   g_hs16);
    cudaGetSymbolAddress((void**)&win_h,  g_win_h);
    cudaGetSymbolAddress((void**)&win_l,  g_win_l);
    cudaGetSymbolAddress((void**)&wout_h, g_wout_h);
    cudaGetSymbolAddress((void**)&wout_l, g_wout_l);
    cudaGetSymbolAddress((void**)&xbuf,   g_x);
    cudaGetSymbolAddress((void**)&ybuf,   g_y);

    cudaFuncSetAttribute(gemm_fp16x2, cudaFuncAttributeMaxDynamicSharedMemorySize, GEMM_SMEM);

    // conversions / splits
    {
        long long n4 = (long long)MROWS * HID / 4;
        convert_fp16<<<(unsigned)(n4 / 256), 256>>>(hs, hs16, n4);
        n4 = (long long)CH * HID / 4;
        split_fp16<<<(unsigned)(n4 / 256), 256>>>(w_in, win_h, win_l, n4);
        n4 = (long long)HID * CH / 4;
        split_fp16<<<(unsigned)(n4 / 256), 256>>>(w_out, wout_h, wout_l, n4);
    }

    // GEMM1: x = hs @ w_in^T + b_in   [16384, 4096]
    {
        dim3 grid(CH / 128, MROWS / 128);   // (32, 128)
        gemm_fp16x2<<<grid, 256, GEMM_SMEM>>>(hs16, win_h, win_l, b_in, xbuf,
                                              MROWS, CH, HID);
    }

    // conv + SiLU -> y (fp16)
    {
        dim3 grid(CH / 256, SEQ / SCH, BATCH);  // (16, 16, 4)
        conv_silu<<<grid, 256>>>(xbuf, conv_w, conv_b, ybuf);
    }

    // GEMM2: out = y @ w_out^T + b_out  [16384, 2048]
    {
        dim3 grid(HID / 128, MROWS / 128);  // (16, 128)
        gemm_fp16x2<<<grid, 256, GEMM_SMEM>>>(ybuf, wout_h, wout_l, b_out, out,
                                              MROWS, HID, CH);
    }
}

// round 5
// speedup vs baseline: 7.8561x; 1.7604x over previous
#include <cuda_runtime.h>
#include <cuda_fp16.h>
#include <cstdint>

// ---------------------------------------------------------------------------
// Problem dims
// ---------------------------------------------------------------------------
#define HID   2048
#define CH    4096
#define SEQ   4096
#define BATCH 4
#define MROWS (BATCH * SEQ)   // 16384

// ---------------------------------------------------------------------------
// Device scratch (allocation-free rule)
// ---------------------------------------------------------------------------
__device__ __half g_hs16  [(size_t)MROWS * HID];   // hs as fp16
__device__ __half g_win16 [(size_t)CH * HID];      // w_in as fp16
__device__ __half g_wout16[(size_t)HID * CH];      // w_out as fp16
__device__ float  g_x     [(size_t)MROWS * CH];    // after in-proj (fp32)
__device__ __half g_y     [(size_t)MROWS * CH];    // conv+silu (fp16)

// ---------------------------------------------------------------------------
// PTX helpers (arch-generic: cp.async / ldmatrix / mma.sync)
// ---------------------------------------------------------------------------
__device__ __forceinline__ uint32_t smem_u32(const void* p) {
    uint32_t a;
    asm("{ .reg .u64 t; cvta.to.shared.u64 t, %1; cvt.u32.u64 %0, t; }" : "=r"(a) : "l"(p));
    return a;
}
__device__ __forceinline__ void cp16(uint32_t dst, const void* src) {
    asm volatile("cp.async.cg.shared.global [%0], [%1], 16;" :: "r"(dst), "l"(src));
}
__device__ __forceinline__ void cp_commit() { asm volatile("cp.async.commit_group;" ::: "memory"); }
__device__ __forceinline__ void cp_wait2()  { asm volatile("cp.async.wait_group 2;"  ::: "memory"); }
__device__ __forceinline__ void cp_wait1()  { asm volatile("cp.async.wait_group 1;"  ::: "memory"); }
__device__ __forceinline__ void cp_wait0()  { asm volatile("cp.async.wait_group 0;"  ::: "memory"); }

__device__ __forceinline__ void ldsm_x4(uint32_t* r, uint32_t addr) {
    asm volatile("ldmatrix.sync.aligned.m8n8.x4.shared.b16 {%0,%1,%2,%3}, [%4];"
        : "=r"(r[0]), "=r"(r[1]), "=r"(r[2]), "=r"(r[3]) : "r"(addr));
}
__device__ __forceinline__ void mma16816(float* c, const uint32_t* a, const uint32_t* b) {
    asm volatile(
        "mma.sync.aligned.m16n8k16.row.col.f32.f16.f16.f32 "
        "{%0,%1,%2,%3}, {%4,%5,%6,%7}, {%8,%9}, {%0,%1,%2,%3};"
        : "+f"(c[0]), "+f"(c[1]), "+f"(c[2]), "+f"(c[3])
        : "r"(a[0]), "r"(a[1]), "r"(a[2]), "r"(a[3]), "r"(b[0]), "r"(b[1]));
}

// ---------------------------------------------------------------------------
// GEMM: C[m,n] = sum_k A[m,k]*B[n,k] + bias[n]   (single-pass fp16, fp32 acc)
// CTA tile 128x128, 8 warps (warp tile 32x64), BK=32, 4-stage cp.async.
// smem/stage: 2 tiles x 128 x 40(fp16) = 20480 B; 4 stages = 81920 B -> occ 2.
// ---------------------------------------------------------------------------
#define BK    32
#define LDA   40
#define MATB  (128 * LDA)                 // 5120 elems / tile
#define STAGE_ELEMS (2 * MATB)            // A, B
#define STAGES 4
#define GEMM_SMEM (STAGES * STAGE_ELEMS * 2)  // 81920 bytes

__global__ void __launch_bounds__(256, 2)
gemm_fp16(const __half* __restrict__ A, const __half* __restrict__ B,
          const float* __restrict__ bias, float* __restrict__ C,
          int M, int N, int K)
{
    extern __shared__ __align__(16) char smraw[];
    const uint32_t sbase = smem_u32(smraw);

    const int tid  = threadIdx.x;
    const int wid  = tid >> 5;
    const int lane = tid & 31;
    const int bm   = blockIdx.y * 128;
    const int bn   = blockIdx.x * 128;
    const int wm   = (wid & 3) * 32;     // warp row offset
    const int wn   = (wid >> 2) * 64;    // warp col offset

    float acc[2][8][4];
#pragma unroll
    for (int i = 0; i < 2; i++)
#pragma unroll
        for (int j = 0; j < 8; j++)
#pragma unroll
            for (int k = 0; k < 4; k++) acc[i][j][k] = 0.0f;

    const int nchunks = K / BK;

    // stage loader: 2 cp16 per thread per matrix (A, B)
    auto load_stage = [&](int slot, int k0) {
        const uint32_t st = sbase + (uint32_t)slot * STAGE_ELEMS * 2;
#pragma unroll
        for (int i = 0; i < 2; i++) {
            const int c   = tid + 256 * i;       // 0..511
            const int row = c >> 2;
            const int kc  = (c & 3) * 8;
            const uint32_t soff = (uint32_t)(row * LDA + kc) * 2;
            cp16(st + soff,            A + (size_t)(bm + row) * K + k0 + kc);
            cp16(st + MATB * 2 + soff, B + (size_t)(bn + row) * K + k0 + kc);
        }
        cp_commit();
    };

    // prologue: 3 stages in flight
    load_stage(0, 0);
    load_stage(1, BK);
    load_stage(2, 2 * BK);

    for (int i = 0; i < nchunks; i++) {
        if (i + 2 < nchunks)      cp_wait2();
        else if (i + 1 < nchunks) cp_wait1();
        else                      cp_wait0();
        __syncthreads();

        if (i + 3 < nchunks) load_stage((i + 3) % STAGES, (i + 3) * BK);

        const uint32_t st = sbase + (uint32_t)(i % STAGES) * STAGE_ELEMS * 2;
        const uint32_t sA = st;
        const uint32_t sB = st + MATB * 2;

#pragma unroll
        for (int kk = 0; kk < 2; kk++) {           // two k16 sub-steps
            uint32_t a[2][4];
#pragma unroll
            for (int mt = 0; mt < 2; mt++) {
                const int row = wm + mt * 16 + (lane & 15);
                const int col = kk * 16 + (lane >> 4) * 8;
                ldsm_x4(a[mt], sA + (uint32_t)(row * LDA + col) * 2);
            }
            uint32_t b[4][4];
#pragma unroll
            for (int q = 0; q < 4; q++) {
                const int nrow = wn + q * 16 + (lane & 7) + ((lane >> 4) << 3);
                const int col  = kk * 16 + ((lane >> 3) & 1) * 8;
                ldsm_x4(b[q], sB + (uint32_t)(nrow * LDA + col) * 2);
            }
#pragma unroll
            for (int mt = 0; mt < 2; mt++)
#pragma unroll
                for (int q = 0; q < 4; q++)
#pragma unroll
                    for (int h = 0; h < 2; h++)
                        mma16816(acc[mt][q * 2 + h], a[mt], &b[q][h * 2]);
        }
        // single barrier per iteration suffices: slot (i+3)%4 was last read
        // in iter i-1, which is ordered by this iteration's __syncthreads.
    }

    // --- epilogue: fused bias ---
    const int r  = lane >> 2;
    const int cc = (lane & 3) * 2;
#pragma unroll
    for (int mt = 0; mt < 2; mt++) {
        const int row0 = bm + wm + mt * 16;
#pragma unroll
        for (int nt = 0; nt < 8; nt++) {
            const int col0 = bn + wn + nt * 8;
            const float2 bv = *reinterpret_cast<const float2*>(bias + col0 + cc);
            float* p0 = C + (size_t)(row0 + r) * N + col0 + cc;
            float* p1 = C + (size_t)(row0 + r + 8) * N + col0 + cc;
            float2 o0, o1;
            o0.x = acc[mt][nt][0] + bv.x;  o0.y = acc[mt][nt][1] + bv.y;
            o1.x = acc[mt][nt][2] + bv.x;  o1.y = acc[mt][nt][3] + bv.y;
            *reinterpret_cast<float2*>(p0) = o0;
            *reinterpret_cast<float2*>(p1) = o1;
        }
    }
}

// ---------------------------------------------------------------------------
// fp32 -> fp16 convert
// ---------------------------------------------------------------------------
__global__ void __launch_bounds__(256)
convert_fp16(const float* __restrict__ src, __half* __restrict__ dst, long long n4)
{
    const long long i = (long long)blockIdx.x * blockDim.x + threadIdx.x;
    if (i >= n4) return;
    const float4 v = reinterpret_cast<const float4*>(src)[i];
    __half2 p0, p1;
    p0.x = __float2half(v.x); p0.y = __float2half(v.y);
    p1.x = __float2half(v.z); p1.y = __float2half(v.w);
    reinterpret_cast<__half2*>(dst)[2 * i]     = p0;
    reinterpret_cast<__half2*>(dst)[2 * i + 1] = p1;
}

// ---------------------------------------------------------------------------
// Causal depthwise conv (K=4) + bias + SiLU -> fp16
// ---------------------------------------------------------------------------
#define SCH 256
__global__ void __launch_bounds__(256)
conv_silu(const float* __restrict__ x, const float* __restrict__ cw,
          const float* __restrict__ cb, __half* __restrict__ y)
{
    const int c  = blockIdx.x * 256 + threadIdx.x;   // channel
    const int b  = blockIdx.z;
    const int s0 = blockIdx.y * SCH;

    const float4 w4 = *reinterpret_cast<const float4*>(cw + (size_t)c * 4);
    const float bias = cb[c];
    const size_t base = ((size_t)b * SEQ) * CH + c;

    float xm3, xm2, xm1;
    if (s0 == 0) { xm3 = xm2 = xm1 = 0.0f; }
    else {
        xm3 = x[base + (size_t)(s0 - 3) * CH];
        xm2 = x[base + (size_t)(s0 - 2) * CH];
        xm1 = x[base + (size_t)(s0 - 1) * CH];
    }

    for (int s = s0; s < s0 + SCH; s++) {
        const float xc = x[base + (size_t)s * CH];
        float acc = bias;
        acc = fmaf(w4.x, xm3, acc);
        acc = fmaf(w4.y, xm2, acc);
        acc = fmaf(w4.z, xm1, acc);
        acc = fmaf(w4.w, xc,  acc);
        const float v = acc / (1.0f + __expf(-acc));
        y[base + (size_t)s * CH] = __float2half(v);
        xm3 = xm2; xm2 = xm1; xm1 = xc;
    }
}

// ---------------------------------------------------------------------------
// Launch: hidden_states, w_in, b_in, conv_w, conv_b, w_out, b_out
// ---------------------------------------------------------------------------
extern "C" void kernel_launch(void* const* d_in, const int* in_sizes, int n_in,
                              void* d_out, int out_size)
{
    const float* hs     = (const float*)d_in[0];
    const float* w_in   = (const float*)d_in[1];
    const float* b_in   = (const float*)d_in[2];
    const float* conv_w = (const float*)d_in[3];
    const float* conv_b = (const float*)d_in[4];
    const float* w_out  = (const float*)d_in[5];
    const float* b_out  = (const float*)d_in[6];
    float* out = (float*)d_out;

    __half *hs16, *win16, *wout16, *ybuf;
    float *xbuf;
    cudaGetSymbolAddress((void**)&hs16,   g_hs16);
    cudaGetSymbolAddress((void**)&win16,  g_win16);
    cudaGetSymbolAddress((void**)&wout16, g_wout16);
    cudaGetSymbolAddress((void**)&xbuf,   g_x);
    cudaGetSymbolAddress((void**)&ybuf,   g_y);

    cudaFuncSetAttribute(gemm_fp16, cudaFuncAttributeMaxDynamicSharedMemorySize, GEMM_SMEM);

    // fp16 conversions
    {
        long long n4 = (long long)MROWS * HID / 4;
        convert_fp16<<<(unsigned)(n4 / 256), 256>>>(hs, hs16, n4);
        n4 = (long long)CH * HID / 4;
        convert_fp16<<<(unsigned)(n4 / 256), 256>>>(w_in, win16, n4);
        n4 = (long long)HID * CH / 4;
        convert_fp16<<<(unsigned)(n4 / 256), 256>>>(w_out, wout16, n4);
    }

    // GEMM1: x = hs @ w_in^T + b_in   [16384, 4096]
    {
        dim3 grid(CH / 128, MROWS / 128);   // (32, 128)
        gemm_fp16<<<grid, 256, GEMM_SMEM>>>(hs16, win16, b_in, xbuf, MROWS, CH, HID);
    }

    // conv + SiLU -> y (fp16)
    {
        dim3 grid(CH / 256, SEQ / SCH, BATCH);  // (16, 16, 4)
        conv_silu<<<grid, 256>>>(xbuf, conv_w, conv_b, ybuf);
    }

    // GEMM2: out = y @ w_out^T + b_out  [16384, 2048]
    {
        dim3 grid(HID / 128, MROWS / 128);  // (16, 128)
        gemm_fp16<<<grid, 256, GEMM_SMEM>>>(ybuf, wout16, b_out, out, MROWS, HID, CH);
    }
}

// round 6
// speedup vs baseline: 8.8182x; 1.1225x over previous
#include <cuda_runtime.h>
#include <cuda_fp16.h>
#include <cstdint>

// ---------------------------------------------------------------------------
// Problem dims
// ---------------------------------------------------------------------------
#define HID   2048
#define CH    4096
#define SEQ   4096
#define BATCH 4
#define MROWS (BATCH * SEQ)   // 16384

// ---------------------------------------------------------------------------
// Device scratch (allocation-free rule)
// ---------------------------------------------------------------------------
__device__ __half g_hs16  [(size_t)MROWS * HID];   // hs as fp16
__device__ __half g_win16 [(size_t)CH * HID];      // w_in as fp16
__device__ __half g_wout16[(size_t)HID * CH];      // w_out as fp16
__device__ float  g_x     [(size_t)MROWS * CH];    // after in-proj (fp32)
__device__ __half g_y     [(size_t)MROWS * CH];    // conv+silu (fp16)

// ---------------------------------------------------------------------------
// PTX helpers (arch-generic: cp.async / ldmatrix / mma.sync)
// ---------------------------------------------------------------------------
__device__ __forceinline__ uint32_t smem_u32(const void* p) {
    uint32_t a;
    asm("{ .reg .u64 t; cvta.to.shared.u64 t, %1; cvt.u32.u64 %0, t; }" : "=r"(a) : "l"(p));
    return a;
}
__device__ __forceinline__ void cp16(uint32_t dst, const void* src) {
    asm volatile("cp.async.cg.shared.global [%0], [%1], 16;" :: "r"(dst), "l"(src));
}
__device__ __forceinline__ void cp_commit() { asm volatile("cp.async.commit_group;" ::: "memory"); }
__device__ __forceinline__ void cp_wait1()  { asm volatile("cp.async.wait_group 1;"  ::: "memory"); }
__device__ __forceinline__ void cp_wait0()  { asm volatile("cp.async.wait_group 0;"  ::: "memory"); }

__device__ __forceinline__ void ldsm_x4(uint32_t* r, uint32_t addr) {
    asm volatile("ldmatrix.sync.aligned.m8n8.x4.shared.b16 {%0,%1,%2,%3}, [%4];"
        : "=r"(r[0]), "=r"(r[1]), "=r"(r[2]), "=r"(r[3]) : "r"(addr));
}
__device__ __forceinline__ void mma16816(float* c, const uint32_t* a, const uint32_t* b) {
    asm volatile(
        "mma.sync.aligned.m16n8k16.row.col.f32.f16.f16.f32 "
        "{%0,%1,%2,%3}, {%4,%5,%6,%7}, {%8,%9}, {%0,%1,%2,%3};"
        : "+f"(c[0]), "+f"(c[1]), "+f"(c[2]), "+f"(c[3])
        : "r"(a[0]), "r"(a[1]), "r"(a[2]), "r"(a[3]), "r"(b[0]), "r"(b[1]));
}

// ---------------------------------------------------------------------------
// GEMM: C[m,n] = sum_k A[m,k]*B[n,k] + bias[n]   (fp16 in, fp32 acc)
// CTA tile 128x128, 8 warps (warp tile 32x64), BK=64, 3-stage cp.async.
// smem/stage: 2 tiles x 128 x 72(fp16) = 36864 B; 3 stages = 110592 B -> occ 2.
// LDA=72 -> 144B row stride -> ldsm 8-row groups hit distinct banks.
// ---------------------------------------------------------------------------
#define BK    64
#define LDA   72
#define MATB  (128 * LDA)                 // 9216 elems / tile
#define STAGE_ELEMS (2 * MATB)            // A, B
#define STAGES 3
#define GEMM_SMEM (STAGES * STAGE_ELEMS * 2)  // 110592 bytes

__global__ void __launch_bounds__(256, 2)
gemm_fp16(const __half* __restrict__ A, const __half* __restrict__ B,
          const float* __restrict__ bias, float* __restrict__ C,
          int M, int N, int K)
{
    extern __shared__ __align__(16) char smraw[];
    const uint32_t sbase = smem_u32(smraw);

    const int tid  = threadIdx.x;
    const int wid  = tid >> 5;
    const int lane = tid & 31;
    const int bm   = blockIdx.y * 128;
    const int bn   = blockIdx.x * 128;
    const int wm   = (wid & 3) * 32;     // warp row offset
    const int wn   = (wid >> 2) * 64;    // warp col offset

    float acc[2][8][4];
#pragma unroll
    for (int i = 0; i < 2; i++)
#pragma unroll
        for (int j = 0; j < 8; j++)
#pragma unroll
            for (int k = 0; k < 4; k++) acc[i][j][k] = 0.0f;

    const int nchunks = K / BK;

    // stage loader: 128 rows x 64 cols fp16 per matrix = 1024 cp16 / 256 thr
    auto load_stage = [&](int slot, int k0) {
        const uint32_t st = sbase + (uint32_t)slot * STAGE_ELEMS * 2;
#pragma unroll
        for (int i = 0; i < 4; i++) {
            const int c   = tid + 256 * i;       // 0..1023
            const int row = c >> 3;
            const int kc  = (c & 7) * 8;
            const uint32_t soff = (uint32_t)(row * LDA + kc) * 2;
            cp16(st + soff,            A + (size_t)(bm + row) * K + k0 + kc);
            cp16(st + MATB * 2 + soff, B + (size_t)(bn + row) * K + k0 + kc);
        }
        cp_commit();
    };

    // prologue: 2 stages in flight
    load_stage(0, 0);
    load_stage(1, BK);

    for (int i = 0; i < nchunks; i++) {
        if (i + 1 < nchunks) cp_wait1(); else cp_wait0();
        __syncthreads();

        if (i + 2 < nchunks) load_stage((i + 2) % STAGES, (i + 2) * BK);

        const uint32_t st = sbase + (uint32_t)(i % STAGES) * STAGE_ELEMS * 2;
        const uint32_t sA = st;
        const uint32_t sB = st + MATB * 2;

#pragma unroll
        for (int kk = 0; kk < 4; kk++) {           // four k16 sub-steps
            uint32_t a[2][4];
#pragma unroll
            for (int mt = 0; mt < 2; mt++) {
                const int row = wm + mt * 16 + (lane & 15);
                const int col = kk * 16 + (lane >> 4) * 8;
                ldsm_x4(a[mt], sA + (uint32_t)(row * LDA + col) * 2);
            }
            uint32_t b[4][4];
#pragma unroll
            for (int q = 0; q < 4; q++) {
                const int nrow = wn + q * 16 + (lane & 7) + ((lane >> 4) << 3);
                const int col  = kk * 16 + ((lane >> 3) & 1) * 8;
                ldsm_x4(b[q], sB + (uint32_t)(nrow * LDA + col) * 2);
            }
#pragma unroll
            for (int mt = 0; mt < 2; mt++)
#pragma unroll
                for (int q = 0; q < 4; q++)
#pragma unroll
                    for (int h = 0; h < 2; h++)
                        mma16816(acc[mt][q * 2 + h], a[mt], &b[q][h * 2]);
        }
        // single barrier per iteration: slot (i+2)%3 was last read in iter
        // i-1, ordered by this iteration's __syncthreads.
    }

    // --- epilogue: fused bias ---
    const int r  = lane >> 2;
    const int cc = (lane & 3) * 2;
#pragma unroll
    for (int mt = 0; mt < 2; mt++) {
        const int row0 = bm + wm + mt * 16;
#pragma unroll
        for (int nt = 0; nt < 8; nt++) {
            const int col0 = bn + wn + nt * 8;
            const float2 bv = *reinterpret_cast<const float2*>(bias + col0 + cc);
            float* p0 = C + (size_t)(row0 + r) * N + col0 + cc;
            float* p1 = C + (size_t)(row0 + r + 8) * N + col0 + cc;
            float2 o0, o1;
            o0.x = acc[mt][nt][0] + bv.x;  o0.y = acc[mt][nt][1] + bv.y;
            o1.x = acc[mt][nt][2] + bv.x;  o1.y = acc[mt][nt][3] + bv.y;
            *reinterpret_cast<float2*>(p0) = o0;
            *reinterpret_cast<float2*>(p1) = o1;
        }
    }
}

// ---------------------------------------------------------------------------
// fp32 -> fp16 convert
// ---------------------------------------------------------------------------
__global__ void __launch_bounds__(256)
convert_fp16(const float* __restrict__ src, __half* __restrict__ dst, long long n4)
{
    const long long i = (long long)blockIdx.x * blockDim.x + threadIdx.x;
    if (i >= n4) return;
    const float4 v = reinterpret_cast<const float4*>(src)[i];
    __half2 p0, p1;
    p0.x = __float2half(v.x); p0.y = __float2half(v.y);
    p1.x = __float2half(v.z); p1.y = __float2half(v.w);
    reinterpret_cast<__half2*>(dst)[2 * i]     = p0;
    reinterpret_cast<__half2*>(dst)[2 * i + 1] = p1;
}

// ---------------------------------------------------------------------------
// Causal depthwise conv (K=4) + bias + SiLU -> fp16
// ---------------------------------------------------------------------------
#define SCH 256
__global__ void __launch_bounds__(256)
conv_silu(const float* __restrict__ x, const float* __restrict__ cw,
          const float* __restrict__ cb, __half* __restrict__ y)
{
    const int c  = blockIdx.x * 256 + threadIdx.x;   // channel
    const int b  = blockIdx.z;
    const int s0 = blockIdx.y * SCH;

    const float4 w4 = *reinterpret_cast<const float4*>(cw + (size_t)c * 4);
    const float bias = cb[c];
    const size_t base = ((size_t)b * SEQ) * CH + c;

    float xm3, xm2, xm1;
    if (s0 == 0) { xm3 = xm2 = xm1 = 0.0f; }
    else {
        xm3 = x[base + (size_t)(s0 - 3) * CH];
        xm2 = x[base + (size_t)(s0 - 2) * CH];
        xm1 = x[base + (size_t)(s0 - 1) * CH];
    }

    for (int s = s0; s < s0 + SCH; s++) {
        const float xc = x[base + (size_t)s * CH];
        float acc = bias;
        acc = fmaf(w4.x, xm3, acc);
        acc = fmaf(w4.y, xm2, acc);
        acc = fmaf(w4.z, xm1, acc);
        acc = fmaf(w4.w, xc,  acc);
        const float v = acc / (1.0f + __expf(-acc));
        y[base + (size_t)s * CH] = __float2half(v);
        xm3 = xm2; xm2 = xm1; xm1 = xc;
    }
}

// ---------------------------------------------------------------------------
// Launch: hidden_states, w_in, b_in, conv_w, conv_b, w_out, b_out
// ---------------------------------------------------------------------------
extern "C" void kernel_launch(void* const* d_in, const int* in_sizes, int n_in,
                              void* d_out, int out_size)
{
    const float* hs     = (const float*)d_in[0];
    const float* w_in   = (const float*)d_in[1];
    const float* b_in   = (const float*)d_in[2];
    const float* conv_w = (const float*)d_in[3];
    const float* conv_b = (const float*)d_in[4];
    const float* w_out  = (const float*)d_in[5];
    const float* b_out  = (const float*)d_in[6];
    float* out = (float*)d_out;

    __half *hs16, *win16, *wout16, *ybuf;
    float *xbuf;
    cudaGetSymbolAddress((void**)&hs16,   g_hs16);
    cudaGetSymbolAddress((void**)&win16,  g_win16);
    cudaGetSymbolAddress((void**)&wout16, g_wout16);
    cudaGetSymbolAddress((void**)&xbuf,   g_x);
    cudaGetSymbolAddress((void**)&ybuf,   g_y);

    cudaFuncSetAttribute(gemm_fp16, cudaFuncAttributeMaxDynamicSharedMemorySize, GEMM_SMEM);

    // fp16 conversions
    {
        long long n4 = (long long)MROWS * HID / 4;
        convert_fp16<<<(unsigned)(n4 / 256), 256>>>(hs, hs16, n4);
        n4 = (long long)CH * HID / 4;
        convert_fp16<<<(unsigned)(n4 / 256), 256>>>(w_in, win16, n4);
        n4 = (long long)HID * CH / 4;
        convert_fp16<<<(unsigned)(n4 / 256), 256>>>(w_out, wout16, n4);
    }

    // GEMM1: x = hs @ w_in^T + b_in   [16384, 4096]
    {
        dim3 grid(CH / 128, MROWS / 128);   // (32, 128)
        gemm_fp16<<<grid, 256, GEMM_SMEM>>>(hs16, win16, b_in, xbuf, MROWS, CH, HID);
    }

    // conv + SiLU -> y (fp16)
    {
        dim3 grid(CH / 256, SEQ / SCH, BATCH);  // (16, 16, 4)
        conv_silu<<<grid, 256>>>(xbuf, conv_w, conv_b, ybuf);
    }

    // GEMM2: out = y @ w_out^T + b_out  [16384, 2048]
    {
        dim3 grid(HID / 128, MROWS / 128);  // (16, 128)
        gemm_fp16<<<grid, 256, GEMM_SMEM>>>(ybuf, wout16, b_out, out, MROWS, HID, CH);
    }
}